// round 14
// baseline (speedup 1.0000x reference)
#include <cuda_runtime.h>
#include <cuda_fp16.h>
#include <cstdint>

#define CH    256
#define KOFF  27
#define MAXN  100000
#define BM    128      // pair-rows per CTA tile
#define KC    32       // K-chunk (8 chunks of 32 over CH=256)
#define NSTAGE 2
#define STATS_BLOCKS 512

// smem layout (bytes) — 2-stage: 38912/CTA -> 3 CTAs/SM within ~128KB budget
#define A_LDM     40                        // halfs: 32 + 8 pad
#define B_LDM     136                       // halfs: 128 + 8 pad
#define A_STAGE_B (BM * A_LDM * 2)          // 10240
#define B_STAGE_B (KC * B_LDM * 2)          // 8704
#define STAGE_B   (A_STAGE_B + B_STAGE_B)   // 18944  (2 stages = 37888)
#define OFF_LISTS (NSTAGE * STAGE_B)        // 37888
#define SMEM_TOT  (OFF_LISTS + 2 * BM * 4)  // 38912

// ---- scratch (device globals; allocation-free) ----
__device__ __half g_h [(size_t)MAXN * CH];     // bn_relu output (fp16)
__device__ float  g_y [(size_t)MAXN * CH];     // conv1 output (fp32)
__device__ __half g_w1h[(size_t)KOFF * CH * CH];
__device__ __half g_w2h[(size_t)KOFF * CH * CH];
__device__ int    g_cnt[KOFF];
__device__ int    g_pin [(size_t)KOFF * MAXN];
__device__ int    g_pout[(size_t)KOFF * MAXN];
__device__ float  g_part[2 * STATS_BLOCKS * CH];
__device__ float  g_scale[CH];
__device__ float  g_shift[CH];

__device__ __forceinline__ uint32_t smem_u32(const void* p) {
    uint32_t a;
    asm("{ .reg .u64 t; cvta.to.shared.u64 t, %1; cvt.u32.u64 %0, t; }" : "=r"(a) : "l"(p));
    return a;
}
__device__ __forceinline__ void cp16(uint32_t dst, const void* src, int src_size) {
    asm volatile("cp.async.cg.shared.global [%0], [%1], 16, %2;"
                 :: "r"(dst), "l"(src), "r"(src_size) : "memory");
}
__device__ __forceinline__ void cp_commit() {
    asm volatile("cp.async.commit_group;" ::: "memory");
}
__device__ __forceinline__ void cp_wait0() {
    asm volatile("cp.async.wait_group 0;" ::: "memory");
}
__device__ __forceinline__ void red_add2(float* p, float a, float b) {
    asm volatile("red.global.add.v2.f32 [%0], {%1, %2};"
                 :: "l"(p), "f"(a), "f"(b) : "memory");
}
__device__ __forceinline__ void ldmx4(uint32_t* r, uint32_t addr) {
    asm volatile("ldmatrix.sync.aligned.m8n8.x4.shared.b16 {%0,%1,%2,%3}, [%4];"
                 : "=r"(r[0]), "=r"(r[1]), "=r"(r[2]), "=r"(r[3]) : "r"(addr));
}
__device__ __forceinline__ void ldmx4_t(uint32_t* r, uint32_t addr) {
    asm volatile("ldmatrix.sync.aligned.m8n8.x4.trans.shared.b16 {%0,%1,%2,%3}, [%4];"
                 : "=r"(r[0]), "=r"(r[1]), "=r"(r[2]), "=r"(r[3]) : "r"(addr));
}
__device__ __forceinline__ void mma16816(float* c, const uint32_t* a, const uint32_t* b) {
    asm volatile("mma.sync.aligned.m16n8k16.row.col.f32.f16.f16.f32 "
                 "{%0,%1,%2,%3}, {%4,%5,%6,%7}, {%8,%9}, {%0,%1,%2,%3};"
                 : "+f"(c[0]), "+f"(c[1]), "+f"(c[2]), "+f"(c[3])
                 : "r"(a[0]), "r"(a[1]), "r"(a[2]), "r"(a[3]), "r"(b[0]), "r"(b[1]));
}

// ---------------- BatchNorm stats: float4 + 4-row MLP ----------------
__global__ void bn_stats_kernel(const float* __restrict__ x, int n) {
    __shared__ float4 sh[2][256];
    const int c4  = threadIdx.x & 63;
    const int sub = threadIdx.x >> 6;
    float4 s  = make_float4(0.f, 0.f, 0.f, 0.f);
    float4 s2 = make_float4(0.f, 0.f, 0.f, 0.f);
#pragma unroll 4
    for (int r = blockIdx.x * 4 + sub; r < n; r += gridDim.x * 4) {
        float4 v = *(const float4*)(x + (size_t)r * CH + c4 * 4);
        s.x += v.x; s.y += v.y; s.z += v.z; s.w += v.w;
        s2.x += v.x * v.x; s2.y += v.y * v.y; s2.z += v.z * v.z; s2.w += v.w * v.w;
    }
    sh[0][threadIdx.x] = s;
    sh[1][threadIdx.x] = s2;
    __syncthreads();
    if (sub == 0) {
#pragma unroll
        for (int i = 1; i < 4; i++) {
            float4 a = sh[0][c4 + 64 * i], b = sh[1][c4 + 64 * i];
            s.x += a.x; s.y += a.y; s.z += a.z; s.w += a.w;
            s2.x += b.x; s2.y += b.y; s2.z += b.z; s2.w += b.w;
        }
        *(float4*)(g_part + blockIdx.x * CH + c4 * 4) = s;
        *(float4*)(g_part + STATS_BLOCKS * CH + blockIdx.x * CH + c4 * 4) = s2;
    }
}

__global__ void bn_finalize_kernel(const float* __restrict__ gamma,
                                   const float* __restrict__ beta, int n) {
    __shared__ float rs[128], rs2[128];
    int c = blockIdx.x, t = threadIdx.x;
    float s = 0.f, s2 = 0.f;
    for (int b = t; b < STATS_BLOCKS; b += 128) {
        s  += g_part[b * CH + c];
        s2 += g_part[STATS_BLOCKS * CH + b * CH + c];
    }
    rs[t] = s; rs2[t] = s2;
    __syncthreads();
    for (int w = 64; w > 0; w >>= 1) {
        if (t < w) { rs[t] += rs[t + w]; rs2[t] += rs2[t + w]; }
        __syncthreads();
    }
    if (t == 0) {
        float mean = rs[0] / (float)n;
        float var  = rs2[0] / (float)n - mean * mean;
        float rstd = rsqrtf(var + 1e-4f);
        float sc = gamma[c] * rstd;
        g_scale[c] = sc;
        g_shift[c] = beta[c] - mean * sc;
    }
}

// bn + relu -> fp16; optional residual-init copy (rescopy->resdst) and zero-fill (zdst)
__global__ void bn_apply_kernel(const float* __restrict__ x, __half* __restrict__ y,
                                const float* __restrict__ rescopy, float* __restrict__ resdst,
                                float* __restrict__ zdst, int n) {
    size_t total4 = (size_t)n * CH / 4;
    const float4 z4 = make_float4(0.f, 0.f, 0.f, 0.f);
    for (size_t i = (size_t)blockIdx.x * blockDim.x + threadIdx.x; i < total4;
         i += (size_t)gridDim.x * blockDim.x) {
        int c0 = (int)(i & (CH / 4 - 1)) * 4;
        float4 v  = ((const float4*)x)[i];
        float4 sc = *(const float4*)(g_scale + c0);
        float4 sh = *(const float4*)(g_shift + c0);
        float a = fmaxf(fmaf(v.x, sc.x, sh.x), 0.f);
        float b = fmaxf(fmaf(v.y, sc.y, sh.y), 0.f);
        float c = fmaxf(fmaf(v.z, sc.z, sh.z), 0.f);
        float d = fmaxf(fmaf(v.w, sc.w, sh.w), 0.f);
        __half2* y2 = (__half2*)(y + i * 4);
        y2[0] = __floats2half2_rn(a, b);
        y2[1] = __floats2half2_rn(c, d);
        if (resdst) ((float4*)resdst)[i] = ((const float4*)rescopy)[i];
        if (zdst)   ((float4*)zdst)[i] = z4;
    }
}

__global__ void w2h_kernel(const float* __restrict__ W, __half* __restrict__ Wh, int total) {
    for (int i = blockIdx.x * blockDim.x + threadIdx.x; i < total;
         i += gridDim.x * blockDim.x)
        Wh[i] = __float2half_rn(W[i]);
}

// ---- rule lists: per offset k, compact (in,out) pairs where neighbor exists ----
__global__ void build_pairs_kernel(const int* __restrict__ nbr, int n) {
    __shared__ int cnt_l[KOFF];
    __shared__ int base_l[KOFF];
    __shared__ short lpos[256 * KOFF];
    int t = threadIdx.x;
    int p = blockIdx.x * 256 + t;
    if (t < KOFF) cnt_l[t] = 0;
    __syncthreads();
    int nb[KOFF];
    if (p < n) {
#pragma unroll
        for (int k = 0; k < KOFF; k++) {
            nb[k] = nbr[p * KOFF + k];
            if (nb[k] >= 0) lpos[t * KOFF + k] = (short)atomicAdd(&cnt_l[k], 1);
        }
    }
    __syncthreads();
    if (t < KOFF) base_l[t] = atomicAdd(&g_cnt[t], cnt_l[t]);
    __syncthreads();
    if (p < n) {
#pragma unroll
        for (int k = 0; k < KOFF; k++) {
            if (nb[k] >= 0) {
                int pos = base_l[k] + (int)lpos[t * KOFF + k];
                g_pin [k * MAXN + pos] = nb[k];
                g_pout[k * MAXN + pos] = p;
            }
        }
    }
}

// ---------------- gather-GEMM-scatter sparse conv ----------------
// grid: (tiles_per_k * KOFF [mt-major], 2 cout halves). CTA: 256 thr, tile 128 pairs x 128 cout.
// mma.sync m16n8k16 + direct register scatter epilogue (red.global.add.v2.f32).
// 2-stage cp.async pipeline (occ 3): wait0 -> sync -> stage(c+1) -> commit -> compute(c).
// RAW: wait0 (self) + sync publish before frag loads of chunk c.
// WAR: stage(c+1) overwrites buf (c+1)%2 = buf of chunk c-1; compute(c-1) precedes this sync.
__global__ __launch_bounds__(256, 3)
void conv_scatter(const __half* __restrict__ x, const __half* __restrict__ W,
                  float* __restrict__ out, int tpk)
{
    extern __shared__ char dyn[];
    const int tid  = threadIdx.x;
    const int wid  = tid >> 5;
    const int lane = tid & 31;
    const int k    = blockIdx.x % KOFF;       // mt-major: empty tiles cluster in tail waves
    const int mt   = blockIdx.x / KOFF;
    const int cnt  = g_cnt[k];
    const int m0   = mt * BM;
    if (m0 >= cnt) return;
    const int rows = min(BM, cnt - m0);
    const int co0  = blockIdx.y * 128;

    int* in_s  = (int*)(dyn + OFF_LISTS);
    int* out_s = in_s + BM;
    const uint32_t base_u = smem_u32(dyn);

    if (tid < BM) {
        int ok = tid < rows;
        in_s [tid] = ok ? g_pin [k * MAXN + m0 + tid] : -1;
        out_s[tid] = ok ? g_pout[k * MAXN + m0 + tid] : -1;
    }
    __syncthreads();

    const __half* wk = W + (size_t)k * CH * CH;

    auto stage = [&](int c) {
        int buf = c & 1;
        int kc  = c * KC;
        uint32_t a_u = base_u + buf * STAGE_B;
        uint32_t b_u = a_u + A_STAGE_B;
#pragma unroll
        for (int i = 0; i < 2; i++) {          // A: 512 x 16B
            int idx = tid + i * 256;
            int row = idx >> 2, c16 = idx & 3;
            int in = in_s[row];
            uint32_t dst = a_u + row * (A_LDM * 2) + c16 * 16;
            const __half* src = x + ((size_t)(in < 0 ? 0 : in) * CH + kc + c16 * 8);
            cp16(dst, src, in < 0 ? 0 : 16);
        }
#pragma unroll
        for (int i = 0; i < 2; i++) {          // B: 512 x 16B (32 rows x 128 cols)
            int idx = tid + i * 256;
            int row = idx >> 4, c16 = idx & 15;
            uint32_t dst = b_u + row * (B_LDM * 2) + c16 * 16;
            const __half* src = wk + ((size_t)(kc + row) * CH + co0 + c16 * 8);
            cp16(dst, src, 16);
        }
    };

    // accumulators: 2 m16 blocks x 8 n8 tiles x 4 floats
    float acc[2][8][4];
#pragma unroll
    for (int i = 0; i < 2; i++)
#pragma unroll
        for (int j = 0; j < 8; j++)
#pragma unroll
            for (int e = 0; e < 4; e++) acc[i][j][e] = 0.f;

    const int wm = wid & 3;      // 32-row group
    const int wn = wid >> 2;     // 64-col group (0..1)

    auto compute = [&](int c) {
        uint32_t a_u = base_u + (c & 1) * STAGE_B;
        uint32_t b_u = a_u + A_STAGE_B;
#pragma unroll
        for (int kk = 0; kk < KC; kk += 16) {
            uint32_t af[2][4];
#pragma unroll
            for (int i = 0; i < 2; i++) {
                uint32_t addr = a_u + ((wm * 32 + i * 16 + (lane & 15)) * A_LDM
                                       + kk + ((lane >> 4) << 3)) * 2;
                ldmx4(af[i], addr);
            }
#pragma unroll
            for (int jn = 0; jn < 4; jn++) {   // n16 blocks within 64 cols
                uint32_t bf[4];
                uint32_t baddr = b_u + ((kk + (lane & 15)) * B_LDM
                                        + wn * 64 + jn * 16 + ((lane >> 4) << 3)) * 2;
                ldmx4_t(bf, baddr);
#pragma unroll
                for (int i = 0; i < 2; i++) {
                    mma16816(acc[i][jn * 2 + 0], af[i], bf);
                    mma16816(acc[i][jn * 2 + 1], af[i], bf + 2);
                }
            }
        }
    };

    stage(0); cp_commit();

    // 2-stage pipeline: single barrier per chunk
#pragma unroll 1
    for (int c = 0; c < 7; c++) {
        cp_wait0();          // self: all committed groups (incl. chunk c) landed
        __syncthreads();     // publish all threads' copies; orders compute(c-1) before stage(c+1)
        stage(c + 1); cp_commit();
        compute(c);
    }
    cp_wait0();
    __syncthreads();
    compute(7);

    // ---- direct register scatter epilogue ----
    // mma m16n8 acc layout: thread holds rows {gid, gid+8}, cols {2*tig, 2*tig+1}
    const int gid = lane >> 2;
    const int tig = lane & 3;
#pragma unroll
    for (int i = 0; i < 2; i++) {
        int rbase = wm * 32 + i * 16 + gid;
        int o0 = out_s[rbase];
        int o1 = out_s[rbase + 8];
        float* p0 = (o0 >= 0) ? out + (size_t)o0 * CH + co0 + wn * 64 + 2 * tig : 0;
        float* p1 = (o1 >= 0) ? out + (size_t)o1 * CH + co0 + wn * 64 + 2 * tig : 0;
#pragma unroll
        for (int j = 0; j < 8; j++) {
            if (p0) red_add2(p0 + j * 8, acc[i][j][0], acc[i][j][1]);
            if (p1) red_add2(p1 + j * 8, acc[i][j][2], acc[i][j][3]);
        }
    }
}

// ---------------- launch ----------------
extern "C" void kernel_launch(void* const* d_in, const int* in_sizes, int n_in,
                              void* d_out, int out_size) {
    const float* feat   = (const float*)d_in[0];
    const int*   nbr    = (const int*)d_in[2];
    const float* W1     = (const float*)d_in[3];
    const float* gamma1 = (const float*)d_in[4];
    const float* beta1  = (const float*)d_in[5];
    const float* W2     = (const float*)d_in[6];
    const float* gamma2 = (const float*)d_in[7];
    const float* beta2  = (const float*)d_in[8];
    float* out = (float*)d_out;

    int n = in_sizes[0] / CH;
    if (n <= 0) return;

    __half *h, *wh1, *wh2;
    float *y;
    int *cntp;
    cudaGetSymbolAddress((void**)&h,    g_h);
    cudaGetSymbolAddress((void**)&y,    g_y);
    cudaGetSymbolAddress((void**)&wh1,  g_w1h);
    cudaGetSymbolAddress((void**)&wh2,  g_w2h);
    cudaGetSymbolAddress((void**)&cntp, g_cnt);

    cudaFuncSetAttribute(conv_scatter, cudaFuncAttributeMaxDynamicSharedMemorySize, SMEM_TOT);

    const int WTOT = KOFF * CH * CH;
    w2h_kernel<<<512, 256>>>(W1, wh1, WTOT);
    w2h_kernel<<<512, 256>>>(W2, wh2, WTOT);

    cudaMemsetAsync(cntp, 0, KOFF * sizeof(int));
    build_pairs_kernel<<<(n + 255) / 256, 256>>>(nbr, n);

    int tpk = (n + BM - 1) / BM;
    dim3 cgrid(KOFF * tpk, 2);

    // stage 1: bn_apply fuses y zero-fill AND residual init (out = feat)
    bn_stats_kernel<<<STATS_BLOCKS, 256>>>(feat, n);
    bn_finalize_kernel<<<CH, 128>>>(gamma1, beta1, n);
    bn_apply_kernel<<<2048, 256>>>(feat, h, feat, out, y, n);
    conv_scatter<<<cgrid, 256, SMEM_TOT>>>(h, wh1, y, tpk);

    // stage 2: plain bn_apply; conv2 scatter-adds onto out (already holds feat)
    bn_stats_kernel<<<STATS_BLOCKS, 256>>>(y, n);
    bn_finalize_kernel<<<CH, 128>>>(gamma2, beta2, n);
    bn_apply_kernel<<<2048, 256>>>(y, h, (const float*)0, (float*)0, (float*)0, n);
    conv_scatter<<<cgrid, 256, SMEM_TOT>>>(h, wh2, out, tpk);
}

// round 15
// speedup vs baseline: 1.2786x; 1.2786x over previous
#include <cuda_runtime.h>
#include <cuda_fp16.h>
#include <cstdint>

#define CH    256
#define KOFF  27
#define MAXN  100000
#define BM    128      // pair-rows per CTA tile
#define KC    32       // K-chunk (8 chunks of 32 over CH=256)
#define NSTAGE 3
#define STATS_BLOCKS 512

// smem layout (bytes) — MUST stay <= ~60KB/CTA: occ-2 requires 2*SMEM <= ~128KB/SM
#define A_LDM     40                        // halfs: 32 + 8 pad
#define B_LDM     136                       // halfs: 128 + 8 pad
#define A_STAGE_B (BM * A_LDM * 2)          // 10240
#define B_STAGE_B (KC * B_LDM * 2)          // 8704
#define STAGE_B   (A_STAGE_B + B_STAGE_B)   // 18944  (3 stages = 56832)
#define OFF_LISTS (NSTAGE * STAGE_B)        // 56832
#define SMEM_TOT  (OFF_LISTS + 2 * BM * 4)  // 57856

// ---- scratch (device globals; allocation-free) ----
__device__ __half g_h [(size_t)MAXN * CH];     // bn_relu output (fp16)
__device__ float  g_y [(size_t)MAXN * CH];     // conv1 output (fp32)
__device__ __half g_w1h[(size_t)KOFF * CH * CH];
__device__ __half g_w2h[(size_t)KOFF * CH * CH];
__device__ int    g_cnt[KOFF];
__device__ int    g_pin [(size_t)KOFF * MAXN];
__device__ int    g_pout[(size_t)KOFF * MAXN];
__device__ float  g_part[2 * STATS_BLOCKS * CH];
__device__ float  g_scale[CH];
__device__ float  g_shift[CH];

__device__ __forceinline__ uint32_t smem_u32(const void* p) {
    uint32_t a;
    asm("{ .reg .u64 t; cvta.to.shared.u64 t, %1; cvt.u32.u64 %0, t; }" : "=r"(a) : "l"(p));
    return a;
}
__device__ __forceinline__ void cp16(uint32_t dst, const void* src, int src_size) {
    asm volatile("cp.async.cg.shared.global [%0], [%1], 16, %2;"
                 :: "r"(dst), "l"(src), "r"(src_size) : "memory");
}
__device__ __forceinline__ void cp_commit() {
    asm volatile("cp.async.commit_group;" ::: "memory");
}
__device__ __forceinline__ void cp_wait1() {
    asm volatile("cp.async.wait_group 1;" ::: "memory");
}
__device__ __forceinline__ void cp_wait0() {
    asm volatile("cp.async.wait_group 0;" ::: "memory");
}
__device__ __forceinline__ void red_add2(float* p, float a, float b) {
    asm volatile("red.global.add.v2.f32 [%0], {%1, %2};"
                 :: "l"(p), "f"(a), "f"(b) : "memory");
}
__device__ __forceinline__ void ldmx4(uint32_t* r, uint32_t addr) {
    asm volatile("ldmatrix.sync.aligned.m8n8.x4.shared.b16 {%0,%1,%2,%3}, [%4];"
                 : "=r"(r[0]), "=r"(r[1]), "=r"(r[2]), "=r"(r[3]) : "r"(addr));
}
__device__ __forceinline__ void ldmx4_t(uint32_t* r, uint32_t addr) {
    asm volatile("ldmatrix.sync.aligned.m8n8.x4.trans.shared.b16 {%0,%1,%2,%3}, [%4];"
                 : "=r"(r[0]), "=r"(r[1]), "=r"(r[2]), "=r"(r[3]) : "r"(addr));
}
__device__ __forceinline__ void mma16816(float* c, const uint32_t* a, const uint32_t* b) {
    asm volatile("mma.sync.aligned.m16n8k16.row.col.f32.f16.f16.f32 "
                 "{%0,%1,%2,%3}, {%4,%5,%6,%7}, {%8,%9}, {%0,%1,%2,%3};"
                 : "+f"(c[0]), "+f"(c[1]), "+f"(c[2]), "+f"(c[3])
                 : "r"(a[0]), "r"(a[1]), "r"(a[2]), "r"(a[3]), "r"(b[0]), "r"(b[1]));
}

// ---------------- BatchNorm stats: float4 + 4-row MLP ----------------
__global__ void bn_stats_kernel(const float* __restrict__ x, int n) {
    __shared__ float4 sh[2][256];
    const int c4  = threadIdx.x & 63;
    const int sub = threadIdx.x >> 6;
    float4 s  = make_float4(0.f, 0.f, 0.f, 0.f);
    float4 s2 = make_float4(0.f, 0.f, 0.f, 0.f);
#pragma unroll 4
    for (int r = blockIdx.x * 4 + sub; r < n; r += gridDim.x * 4) {
        float4 v = *(const float4*)(x + (size_t)r * CH + c4 * 4);
        s.x += v.x; s.y += v.y; s.z += v.z; s.w += v.w;
        s2.x += v.x * v.x; s2.y += v.y * v.y; s2.z += v.z * v.z; s2.w += v.w * v.w;
    }
    sh[0][threadIdx.x] = s;
    sh[1][threadIdx.x] = s2;
    __syncthreads();
    if (sub == 0) {
#pragma unroll
        for (int i = 1; i < 4; i++) {
            float4 a = sh[0][c4 + 64 * i], b = sh[1][c4 + 64 * i];
            s.x += a.x; s.y += a.y; s.z += a.z; s.w += a.w;
            s2.x += b.x; s2.y += b.y; s2.z += b.z; s2.w += b.w;
        }
        *(float4*)(g_part + blockIdx.x * CH + c4 * 4) = s;
        *(float4*)(g_part + STATS_BLOCKS * CH + blockIdx.x * CH + c4 * 4) = s2;
    }
}

__global__ void bn_finalize_kernel(const float* __restrict__ gamma,
                                   const float* __restrict__ beta, int n) {
    __shared__ float rs[128], rs2[128];
    int c = blockIdx.x, t = threadIdx.x;
    float s = 0.f, s2 = 0.f;
    for (int b = t; b < STATS_BLOCKS; b += 128) {
        s  += g_part[b * CH + c];
        s2 += g_part[STATS_BLOCKS * CH + b * CH + c];
    }
    rs[t] = s; rs2[t] = s2;
    __syncthreads();
    for (int w = 64; w > 0; w >>= 1) {
        if (t < w) { rs[t] += rs[t + w]; rs2[t] += rs2[t + w]; }
        __syncthreads();
    }
    if (t == 0) {
        float mean = rs[0] / (float)n;
        float var  = rs2[0] / (float)n - mean * mean;
        float rstd = rsqrtf(var + 1e-4f);
        float sc = gamma[c] * rstd;
        g_scale[c] = sc;
        g_shift[c] = beta[c] - mean * sc;
    }
}

// bn + relu -> fp16; optional residual-init copy (rescopy->resdst) and zero-fill (zdst)
__global__ void bn_apply_kernel(const float* __restrict__ x, __half* __restrict__ y,
                                const float* __restrict__ rescopy, float* __restrict__ resdst,
                                float* __restrict__ zdst, int n) {
    size_t total4 = (size_t)n * CH / 4;
    const float4 z4 = make_float4(0.f, 0.f, 0.f, 0.f);
    for (size_t i = (size_t)blockIdx.x * blockDim.x + threadIdx.x; i < total4;
         i += (size_t)gridDim.x * blockDim.x) {
        int c0 = (int)(i & (CH / 4 - 1)) * 4;
        float4 v  = ((const float4*)x)[i];
        float4 sc = *(const float4*)(g_scale + c0);
        float4 sh = *(const float4*)(g_shift + c0);
        float a = fmaxf(fmaf(v.x, sc.x, sh.x), 0.f);
        float b = fmaxf(fmaf(v.y, sc.y, sh.y), 0.f);
        float c = fmaxf(fmaf(v.z, sc.z, sh.z), 0.f);
        float d = fmaxf(fmaf(v.w, sc.w, sh.w), 0.f);
        __half2* y2 = (__half2*)(y + i * 4);
        y2[0] = __floats2half2_rn(a, b);
        y2[1] = __floats2half2_rn(c, d);
        if (resdst) ((float4*)resdst)[i] = ((const float4*)rescopy)[i];
        if (zdst)   ((float4*)zdst)[i] = z4;
    }
}

// convert BOTH weight tensors in one launch
__global__ void w2h_kernel(const float* __restrict__ W1, __half* __restrict__ Wh1,
                           const float* __restrict__ W2, __half* __restrict__ Wh2, int total) {
    for (int i = blockIdx.x * blockDim.x + threadIdx.x; i < total;
         i += gridDim.x * blockDim.x) {
        Wh1[i] = __float2half_rn(W1[i]);
        Wh2[i] = __float2half_rn(W2[i]);
    }
}

// ---- rule lists: per offset k, compact (in,out) pairs where neighbor exists ----
__global__ void build_pairs_kernel(const int* __restrict__ nbr, int n) {
    __shared__ int cnt_l[KOFF];
    __shared__ int base_l[KOFF];
    __shared__ short lpos[256 * KOFF];
    int t = threadIdx.x;
    int p = blockIdx.x * 256 + t;
    if (t < KOFF) cnt_l[t] = 0;
    __syncthreads();
    int nb[KOFF];
    if (p < n) {
#pragma unroll
        for (int k = 0; k < KOFF; k++) {
            nb[k] = nbr[p * KOFF + k];
            if (nb[k] >= 0) lpos[t * KOFF + k] = (short)atomicAdd(&cnt_l[k], 1);
        }
    }
    __syncthreads();
    if (t < KOFF) base_l[t] = atomicAdd(&g_cnt[t], cnt_l[t]);
    __syncthreads();
    if (p < n) {
#pragma unroll
        for (int k = 0; k < KOFF; k++) {
            if (nb[k] >= 0) {
                int pos = base_l[k] + (int)lpos[t * KOFF + k];
                g_pin [k * MAXN + pos] = nb[k];
                g_pout[k * MAXN + pos] = p;
            }
        }
    }
}

// ---------------- gather-GEMM-scatter sparse conv (r13 proven config) ----------------
// grid: (tiles_per_k * KOFF [mt-major], 2 cout halves). CTA: 256 thr, tile 128 pairs x 128 cout.
// mma.sync m16n8k16 + direct register scatter epilogue (red.global.add.v2.f32).
// 3-stage cp.async pipeline, single barrier per chunk:
//   wait1 -> sync -> stage(c+2) -> commit -> compute(c)
__global__ __launch_bounds__(256, 2)
void conv_scatter(const __half* __restrict__ x, const __half* __restrict__ W,
                  float* __restrict__ out, int tpk)
{
    extern __shared__ char dyn[];
    const int tid  = threadIdx.x;
    const int wid  = tid >> 5;
    const int lane = tid & 31;
    const int k    = blockIdx.x % KOFF;       // mt-major: empty tiles cluster in tail waves
    const int mt   = blockIdx.x / KOFF;
    const int cnt  = g_cnt[k];
    const int m0   = mt * BM;
    if (m0 >= cnt) return;
    const int rows = min(BM, cnt - m0);
    const int co0  = blockIdx.y * 128;

    int* in_s  = (int*)(dyn + OFF_LISTS);
    int* out_s = in_s + BM;
    const uint32_t base_u = smem_u32(dyn);

    if (tid < BM) {
        int ok = tid < rows;
        in_s [tid] = ok ? g_pin [k * MAXN + m0 + tid] : -1;
        out_s[tid] = ok ? g_pout[k * MAXN + m0 + tid] : -1;
    }
    __syncthreads();

    const __half* wk = W + (size_t)k * CH * CH;

    auto stage = [&](int c) {
        int buf = c % NSTAGE;
        int kc  = c * KC;
        uint32_t a_u = base_u + buf * STAGE_B;
        uint32_t b_u = a_u + A_STAGE_B;
#pragma unroll
        for (int i = 0; i < 2; i++) {          // A: 512 x 16B
            int idx = tid + i * 256;
            int row = idx >> 2, c16 = idx & 3;
            int in = in_s[row];
            uint32_t dst = a_u + row * (A_LDM * 2) + c16 * 16;
            const __half* src = x + ((size_t)(in < 0 ? 0 : in) * CH + kc + c16 * 8);
            cp16(dst, src, in < 0 ? 0 : 16);
        }
#pragma unroll
        for (int i = 0; i < 2; i++) {          // B: 512 x 16B (32 rows x 128 cols)
            int idx = tid + i * 256;
            int row = idx >> 4, c16 = idx & 15;
            uint32_t dst = b_u + row * (B_LDM * 2) + c16 * 16;
            const __half* src = wk + ((size_t)(kc + row) * CH + co0 + c16 * 8);
            cp16(dst, src, 16);
        }
    };

    // accumulators: 2 m16 blocks x 8 n8 tiles x 4 floats
    float acc[2][8][4];
#pragma unroll
    for (int i = 0; i < 2; i++)
#pragma unroll
        for (int j = 0; j < 8; j++)
#pragma unroll
            for (int e = 0; e < 4; e++) acc[i][j][e] = 0.f;

    const int wm = wid & 3;      // 32-row group
    const int wn = wid >> 2;     // 64-col group (0..1)

    auto compute = [&](int c) {
        uint32_t a_u = base_u + (c % NSTAGE) * STAGE_B;
        uint32_t b_u = a_u + A_STAGE_B;
#pragma unroll
        for (int kk = 0; kk < KC; kk += 16) {
            // preload ALL fragments for this k-step (6 back-to-back ldmatrix), then 16 MMAs
            uint32_t af[2][4];
            uint32_t bf[4][4];
#pragma unroll
            for (int i = 0; i < 2; i++) {
                uint32_t addr = a_u + ((wm * 32 + i * 16 + (lane & 15)) * A_LDM
                                       + kk + ((lane >> 4) << 3)) * 2;
                ldmx4(af[i], addr);
            }
#pragma unroll
            for (int jn = 0; jn < 4; jn++) {
                uint32_t baddr = b_u + ((kk + (lane & 15)) * B_LDM
                                        + wn * 64 + jn * 16 + ((lane >> 4) << 3)) * 2;
                ldmx4_t(bf[jn], baddr);
            }
#pragma unroll
            for (int jn = 0; jn < 4; jn++)
#pragma unroll
                for (int i = 0; i < 2; i++) {
                    mma16816(acc[i][jn * 2 + 0], af[i], bf[jn]);
                    mma16816(acc[i][jn * 2 + 1], af[i], bf[jn] + 2);
                }
        }
    };

    stage(0); cp_commit();
    stage(1); cp_commit();

    // chunks 0..5: single barrier per chunk
#pragma unroll 1
    for (int c = 0; c < 6; c++) {
        cp_wait1();          // self: group c landed (committed 0..c+1, <=1 pending)
        __syncthreads();     // publish all threads' copies; orders compute(c-1) before stage(c+2)
        stage(c + 2); cp_commit();
        compute(c);
    }
    // tail
    cp_wait1();              // groups 0..6 done
    __syncthreads();
    compute(6);
    cp_wait0();              // group 7 done
    __syncthreads();
    compute(7);

    // ---- direct register scatter epilogue ----
    // mma m16n8 acc layout: thread holds rows {gid, gid+8}, cols {2*tig, 2*tig+1}
    const int gid = lane >> 2;
    const int tig = lane & 3;
#pragma unroll
    for (int i = 0; i < 2; i++) {
        int rbase = wm * 32 + i * 16 + gid;
        int o0 = out_s[rbase];
        int o1 = out_s[rbase + 8];
        float* p0 = (o0 >= 0) ? out + (size_t)o0 * CH + co0 + wn * 64 + 2 * tig : 0;
        float* p1 = (o1 >= 0) ? out + (size_t)o1 * CH + co0 + wn * 64 + 2 * tig : 0;
#pragma unroll
        for (int j = 0; j < 8; j++) {
            if (p0) red_add2(p0 + j * 8, acc[i][j][0], acc[i][j][1]);
            if (p1) red_add2(p1 + j * 8, acc[i][j][2], acc[i][j][3]);
        }
    }
}

// ---------------- launch ----------------
extern "C" void kernel_launch(void* const* d_in, const int* in_sizes, int n_in,
                              void* d_out, int out_size) {
    const float* feat   = (const float*)d_in[0];
    const int*   nbr    = (const int*)d_in[2];
    const float* W1     = (const float*)d_in[3];
    const float* gamma1 = (const float*)d_in[4];
    const float* beta1  = (const float*)d_in[5];
    const float* W2     = (const float*)d_in[6];
    const float* gamma2 = (const float*)d_in[7];
    const float* beta2  = (const float*)d_in[8];
    float* out = (float*)d_out;

    int n = in_sizes[0] / CH;
    if (n <= 0) return;

    __half *h, *wh1, *wh2;
    float *y;
    int *cntp;
    cudaGetSymbolAddress((void**)&h,    g_h);
    cudaGetSymbolAddress((void**)&y,    g_y);
    cudaGetSymbolAddress((void**)&wh1,  g_w1h);
    cudaGetSymbolAddress((void**)&wh2,  g_w2h);
    cudaGetSymbolAddress((void**)&cntp, g_cnt);

    cudaFuncSetAttribute(conv_scatter, cudaFuncAttributeMaxDynamicSharedMemorySize, SMEM_TOT);

    const int WTOT = KOFF * CH * CH;
    w2h_kernel<<<512, 256>>>(W1, wh1, W2, wh2, WTOT);

    cudaMemsetAsync(cntp, 0, KOFF * sizeof(int));
    build_pairs_kernel<<<(n + 255) / 256, 256>>>(nbr, n);

    int tpk = (n + BM - 1) / BM;
    dim3 cgrid(KOFF * tpk, 2);

    // stage 1: bn_apply fuses y zero-fill AND residual init (out = feat)
    bn_stats_kernel<<<STATS_BLOCKS, 256>>>(feat, n);
    bn_finalize_kernel<<<CH, 128>>>(gamma1, beta1, n);
    bn_apply_kernel<<<2048, 256>>>(feat, h, feat, out, y, n);
    conv_scatter<<<cgrid, 256, SMEM_TOT>>>(h, wh1, y, tpk);

    // stage 2: plain bn_apply; conv2 scatter-adds onto out (already holds feat)
    bn_stats_kernel<<<STATS_BLOCKS, 256>>>(y, n);
    bn_finalize_kernel<<<CH, 128>>>(gamma2, beta2, n);
    bn_apply_kernel<<<2048, 256>>>(y, h, (const float*)0, (float*)0, (float*)0, n);
    conv_scatter<<<cgrid, 256, SMEM_TOT>>>(h, wh2, out, tpk);
}

// round 16
// speedup vs baseline: 1.3641x; 1.0669x over previous
#include <cuda_runtime.h>
#include <cuda_fp16.h>
#include <cstdint>

#define CH    256
#define KOFF  27
#define MAXN  100000
#define BM    128      // pair-rows per CTA tile
#define KC    32       // K-chunk (8 chunks of 32 over CH=256)
#define NSTAGE 3
#define STATS_BLOCKS 512

// smem layout (bytes) — MUST stay <= ~60KB/CTA: occ-2 requires 2*SMEM <= ~128KB/SM
#define A_LDM     40                        // halfs: 32 + 8 pad
#define B_LDM     136                       // halfs: 128 + 8 pad
#define A_STAGE_B (BM * A_LDM * 2)          // 10240
#define B_STAGE_B (KC * B_LDM * 2)          // 8704
#define STAGE_B   (A_STAGE_B + B_STAGE_B)   // 18944  (3 stages = 56832)
#define OFF_LISTS (NSTAGE * STAGE_B)        // 56832
#define SMEM_TOT  (OFF_LISTS + 2 * BM * 4)  // 57856

// ---- scratch (device globals; allocation-free) ----
__device__ __half g_h [(size_t)MAXN * CH];     // bn_relu output (fp16)
__device__ float  g_y [(size_t)MAXN * CH];     // conv1 output buffer (used as fp16)
__device__ __half g_w1h[(size_t)KOFF * CH * CH];
__device__ __half g_w2h[(size_t)KOFF * CH * CH];
__device__ int    g_cnt[KOFF];
__device__ int    g_pin [(size_t)KOFF * MAXN];
__device__ int    g_pout[(size_t)KOFF * MAXN];
__device__ float  g_part[2 * STATS_BLOCKS * CH];
__device__ float  g_scale[CH];
__device__ float  g_shift[CH];

__device__ __forceinline__ uint32_t smem_u32(const void* p) {
    uint32_t a;
    asm("{ .reg .u64 t; cvta.to.shared.u64 t, %1; cvt.u32.u64 %0, t; }" : "=r"(a) : "l"(p));
    return a;
}
__device__ __forceinline__ void cp16(uint32_t dst, const void* src, int src_size) {
    asm volatile("cp.async.cg.shared.global [%0], [%1], 16, %2;"
                 :: "r"(dst), "l"(src), "r"(src_size) : "memory");
}
__device__ __forceinline__ void cp_commit() {
    asm volatile("cp.async.commit_group;" ::: "memory");
}
__device__ __forceinline__ void cp_wait1() {
    asm volatile("cp.async.wait_group 1;" ::: "memory");
}
__device__ __forceinline__ void cp_wait0() {
    asm volatile("cp.async.wait_group 0;" ::: "memory");
}
// scatter-add 2 consecutive floats: fp32 target -> red.v2.f32; fp16 target -> red.f16x2
__device__ __forceinline__ void scatter2(float* p, float a, float b) {
    asm volatile("red.global.add.v2.f32 [%0], {%1, %2};"
                 :: "l"(p), "f"(a), "f"(b) : "memory");
}
__device__ __forceinline__ void scatter2(__half* p, float a, float b) {
    __half2 v = __floats2half2_rn(a, b);
    asm volatile("red.global.add.noftz.f16x2 [%0], %1;"
                 :: "l"(p), "r"(*(uint32_t*)&v) : "memory");
}
__device__ __forceinline__ void ldmx4(uint32_t* r, uint32_t addr) {
    asm volatile("ldmatrix.sync.aligned.m8n8.x4.shared.b16 {%0,%1,%2,%3}, [%4];"
                 : "=r"(r[0]), "=r"(r[1]), "=r"(r[2]), "=r"(r[3]) : "r"(addr));
}
__device__ __forceinline__ void ldmx4_t(uint32_t* r, uint32_t addr) {
    asm volatile("ldmatrix.sync.aligned.m8n8.x4.trans.shared.b16 {%0,%1,%2,%3}, [%4];"
                 : "=r"(r[0]), "=r"(r[1]), "=r"(r[2]), "=r"(r[3]) : "r"(addr));
}
__device__ __forceinline__ void mma16816(float* c, const uint32_t* a, const uint32_t* b) {
    asm volatile("mma.sync.aligned.m16n8k16.row.col.f32.f16.f16.f32 "
                 "{%0,%1,%2,%3}, {%4,%5,%6,%7}, {%8,%9}, {%0,%1,%2,%3};"
                 : "+f"(c[0]), "+f"(c[1]), "+f"(c[2]), "+f"(c[3])
                 : "r"(a[0]), "r"(a[1]), "r"(a[2]), "r"(a[3]), "r"(b[0]), "r"(b[1]));
}

// ---------------- BatchNorm stats (fp32 input) ----------------
__global__ void bn_stats_kernel(const float* __restrict__ x, int n) {
    __shared__ float4 sh[2][256];
    const int c4  = threadIdx.x & 63;
    const int sub = threadIdx.x >> 6;
    float4 s  = make_float4(0.f, 0.f, 0.f, 0.f);
    float4 s2 = make_float4(0.f, 0.f, 0.f, 0.f);
#pragma unroll 4
    for (int r = blockIdx.x * 4 + sub; r < n; r += gridDim.x * 4) {
        float4 v = *(const float4*)(x + (size_t)r * CH + c4 * 4);
        s.x += v.x; s.y += v.y; s.z += v.z; s.w += v.w;
        s2.x += v.x * v.x; s2.y += v.y * v.y; s2.z += v.z * v.z; s2.w += v.w * v.w;
    }
    sh[0][threadIdx.x] = s;
    sh[1][threadIdx.x] = s2;
    __syncthreads();
    if (sub == 0) {
#pragma unroll
        for (int i = 1; i < 4; i++) {
            float4 a = sh[0][c4 + 64 * i], b = sh[1][c4 + 64 * i];
            s.x += a.x; s.y += a.y; s.z += a.z; s.w += a.w;
            s2.x += b.x; s2.y += b.y; s2.z += b.z; s2.w += b.w;
        }
        *(float4*)(g_part + blockIdx.x * CH + c4 * 4) = s;
        *(float4*)(g_part + STATS_BLOCKS * CH + blockIdx.x * CH + c4 * 4) = s2;
    }
}

// ---------------- BatchNorm stats (fp16 input) ----------------
__global__ void bn_stats_h_kernel(const __half* __restrict__ x, int n) {
    __shared__ float4 sh[2][256];
    const int c4  = threadIdx.x & 63;
    const int sub = threadIdx.x >> 6;
    float4 s  = make_float4(0.f, 0.f, 0.f, 0.f);
    float4 s2 = make_float4(0.f, 0.f, 0.f, 0.f);
#pragma unroll 4
    for (int r = blockIdx.x * 4 + sub; r < n; r += gridDim.x * 4) {
        uint2 raw = *(const uint2*)(x + (size_t)r * CH + c4 * 4);
        float2 f0 = __half22float2(*(__half2*)&raw.x);
        float2 f1 = __half22float2(*(__half2*)&raw.y);
        s.x += f0.x; s.y += f0.y; s.z += f1.x; s.w += f1.y;
        s2.x += f0.x * f0.x; s2.y += f0.y * f0.y; s2.z += f1.x * f1.x; s2.w += f1.y * f1.y;
    }
    sh[0][threadIdx.x] = s;
    sh[1][threadIdx.x] = s2;
    __syncthreads();
    if (sub == 0) {
#pragma unroll
        for (int i = 1; i < 4; i++) {
            float4 a = sh[0][c4 + 64 * i], b = sh[1][c4 + 64 * i];
            s.x += a.x; s.y += a.y; s.z += a.z; s.w += a.w;
            s2.x += b.x; s2.y += b.y; s2.z += b.z; s2.w += b.w;
        }
        *(float4*)(g_part + blockIdx.x * CH + c4 * 4) = s;
        *(float4*)(g_part + STATS_BLOCKS * CH + blockIdx.x * CH + c4 * 4) = s2;
    }
}

__global__ void bn_finalize_kernel(const float* __restrict__ gamma,
                                   const float* __restrict__ beta, int n) {
    __shared__ float rs[128], rs2[128];
    int c = blockIdx.x, t = threadIdx.x;
    float s = 0.f, s2 = 0.f;
    for (int b = t; b < STATS_BLOCKS; b += 128) {
        s  += g_part[b * CH + c];
        s2 += g_part[STATS_BLOCKS * CH + b * CH + c];
    }
    rs[t] = s; rs2[t] = s2;
    __syncthreads();
    for (int w = 64; w > 0; w >>= 1) {
        if (t < w) { rs[t] += rs[t + w]; rs2[t] += rs2[t + w]; }
        __syncthreads();
    }
    if (t == 0) {
        float mean = rs[0] / (float)n;
        float var  = rs2[0] / (float)n - mean * mean;
        float rstd = rsqrtf(var + 1e-4f);
        float sc = gamma[c] * rstd;
        g_scale[c] = sc;
        g_shift[c] = beta[c] - mean * sc;
    }
}

// stage1: bn+relu fp32->fp16 h; also out=feat residual init and y fp16 zero-fill
__global__ void bn_apply_kernel(const float* __restrict__ x, __half* __restrict__ y,
                                const float* __restrict__ rescopy, float* __restrict__ resdst,
                                __half* __restrict__ zdst, int n) {
    size_t total4 = (size_t)n * CH / 4;
    for (size_t i = (size_t)blockIdx.x * blockDim.x + threadIdx.x; i < total4;
         i += (size_t)gridDim.x * blockDim.x) {
        int c0 = (int)(i & (CH / 4 - 1)) * 4;
        float4 v  = ((const float4*)x)[i];
        float4 sc = *(const float4*)(g_scale + c0);
        float4 sh = *(const float4*)(g_shift + c0);
        float a = fmaxf(fmaf(v.x, sc.x, sh.x), 0.f);
        float b = fmaxf(fmaf(v.y, sc.y, sh.y), 0.f);
        float c = fmaxf(fmaf(v.z, sc.z, sh.z), 0.f);
        float d = fmaxf(fmaf(v.w, sc.w, sh.w), 0.f);
        __half2* y2 = (__half2*)(y + i * 4);
        y2[0] = __floats2half2_rn(a, b);
        y2[1] = __floats2half2_rn(c, d);
        if (resdst) ((float4*)resdst)[i] = ((const float4*)rescopy)[i];
        if (zdst)   ((uint2*)zdst)[i] = make_uint2(0u, 0u);
    }
}

// stage2: bn+relu fp16 y -> fp16 h
__global__ void bn_apply_h_kernel(const __half* __restrict__ x, __half* __restrict__ y, int n) {
    size_t total4 = (size_t)n * CH / 4;
    for (size_t i = (size_t)blockIdx.x * blockDim.x + threadIdx.x; i < total4;
         i += (size_t)gridDim.x * blockDim.x) {
        int c0 = (int)(i & (CH / 4 - 1)) * 4;
        uint2 raw = ((const uint2*)x)[i];
        float2 f0 = __half22float2(*(__half2*)&raw.x);
        float2 f1 = __half22float2(*(__half2*)&raw.y);
        float4 sc = *(const float4*)(g_scale + c0);
        float4 sh = *(const float4*)(g_shift + c0);
        float a = fmaxf(fmaf(f0.x, sc.x, sh.x), 0.f);
        float b = fmaxf(fmaf(f0.y, sc.y, sh.y), 0.f);
        float c = fmaxf(fmaf(f1.x, sc.z, sh.z), 0.f);
        float d = fmaxf(fmaf(f1.y, sc.w, sh.w), 0.f);
        __half2* y2 = (__half2*)(y + i * 4);
        y2[0] = __floats2half2_rn(a, b);
        y2[1] = __floats2half2_rn(c, d);
    }
}

// convert BOTH weight tensors in one launch
__global__ void w2h_kernel(const float* __restrict__ W1, __half* __restrict__ Wh1,
                           const float* __restrict__ W2, __half* __restrict__ Wh2, int total) {
    for (int i = blockIdx.x * blockDim.x + threadIdx.x; i < total;
         i += gridDim.x * blockDim.x) {
        Wh1[i] = __float2half_rn(W1[i]);
        Wh2[i] = __float2half_rn(W2[i]);
    }
}

// ---- rule lists: per offset k, compact (in,out) pairs where neighbor exists ----
__global__ void build_pairs_kernel(const int* __restrict__ nbr, int n) {
    __shared__ int cnt_l[KOFF];
    __shared__ int base_l[KOFF];
    __shared__ short lpos[256 * KOFF];
    int t = threadIdx.x;
    int p = blockIdx.x * 256 + t;
    if (t < KOFF) cnt_l[t] = 0;
    __syncthreads();
    int nb[KOFF];
    if (p < n) {
#pragma unroll
        for (int k = 0; k < KOFF; k++) {
            nb[k] = nbr[p * KOFF + k];
            if (nb[k] >= 0) lpos[t * KOFF + k] = (short)atomicAdd(&cnt_l[k], 1);
        }
    }
    __syncthreads();
    if (t < KOFF) base_l[t] = atomicAdd(&g_cnt[t], cnt_l[t]);
    __syncthreads();
    if (p < n) {
#pragma unroll
        for (int k = 0; k < KOFF; k++) {
            if (nb[k] >= 0) {
                int pos = base_l[k] + (int)lpos[t * KOFF + k];
                g_pin [k * MAXN + pos] = nb[k];
                g_pout[k * MAXN + pos] = p;
            }
        }
    }
}

// ---------------- gather-GEMM-scatter sparse conv (templated output type) ----------------
// grid: (tiles_per_k * KOFF [mt-major], 2 cout halves). CTA: 256 thr, tile 128 pairs x 128 cout.
// mma.sync m16n8k16 + direct register scatter epilogue (red.v2.f32 or red.f16x2).
// 3-stage cp.async pipeline, single barrier per chunk:
//   wait1 -> sync -> stage(c+2) -> commit -> compute(c)
template <typename OutT>
__global__ __launch_bounds__(256, 2)
void conv_scatter(const __half* __restrict__ x, const __half* __restrict__ W,
                  OutT* __restrict__ out, int tpk)
{
    extern __shared__ char dyn[];
    const int tid  = threadIdx.x;
    const int wid  = tid >> 5;
    const int lane = tid & 31;
    const int k    = blockIdx.x % KOFF;       // mt-major: empty tiles cluster in tail waves
    const int mt   = blockIdx.x / KOFF;
    const int cnt  = g_cnt[k];
    const int m0   = mt * BM;
    if (m0 >= cnt) return;
    const int rows = min(BM, cnt - m0);
    const int co0  = blockIdx.y * 128;

    int* in_s  = (int*)(dyn + OFF_LISTS);
    int* out_s = in_s + BM;
    const uint32_t base_u = smem_u32(dyn);

    if (tid < BM) {
        int ok = tid < rows;
        in_s [tid] = ok ? g_pin [k * MAXN + m0 + tid] : -1;
        out_s[tid] = ok ? g_pout[k * MAXN + m0 + tid] : -1;
    }
    __syncthreads();

    const __half* wk = W + (size_t)k * CH * CH;

    auto stage = [&](int c) {
        int buf = c % NSTAGE;
        int kc  = c * KC;
        uint32_t a_u = base_u + buf * STAGE_B;
        uint32_t b_u = a_u + A_STAGE_B;
#pragma unroll
        for (int i = 0; i < 2; i++) {          // A: 512 x 16B
            int idx = tid + i * 256;
            int row = idx >> 2, c16 = idx & 3;
            int in = in_s[row];
            uint32_t dst = a_u + row * (A_LDM * 2) + c16 * 16;
            const __half* src = x + ((size_t)(in < 0 ? 0 : in) * CH + kc + c16 * 8);
            cp16(dst, src, in < 0 ? 0 : 16);
        }
#pragma unroll
        for (int i = 0; i < 2; i++) {          // B: 512 x 16B (32 rows x 128 cols)
            int idx = tid + i * 256;
            int row = idx >> 4, c16 = idx & 15;
            uint32_t dst = b_u + row * (B_LDM * 2) + c16 * 16;
            const __half* src = wk + ((size_t)(kc + row) * CH + co0 + c16 * 8);
            cp16(dst, src, 16);
        }
    };

    // accumulators: 2 m16 blocks x 8 n8 tiles x 4 floats
    float acc[2][8][4];
#pragma unroll
    for (int i = 0; i < 2; i++)
#pragma unroll
        for (int j = 0; j < 8; j++)
#pragma unroll
            for (int e = 0; e < 4; e++) acc[i][j][e] = 0.f;

    const int wm = wid & 3;      // 32-row group
    const int wn = wid >> 2;     // 64-col group (0..1)

    auto compute = [&](int c) {
        uint32_t a_u = base_u + (c % NSTAGE) * STAGE_B;
        uint32_t b_u = a_u + A_STAGE_B;
#pragma unroll
        for (int kk = 0; kk < KC; kk += 16) {
            uint32_t af[2][4];
            uint32_t bf[4][4];
#pragma unroll
            for (int i = 0; i < 2; i++) {
                uint32_t addr = a_u + ((wm * 32 + i * 16 + (lane & 15)) * A_LDM
                                       + kk + ((lane >> 4) << 3)) * 2;
                ldmx4(af[i], addr);
            }
#pragma unroll
            for (int jn = 0; jn < 4; jn++) {
                uint32_t baddr = b_u + ((kk + (lane & 15)) * B_LDM
                                        + wn * 64 + jn * 16 + ((lane >> 4) << 3)) * 2;
                ldmx4_t(bf[jn], baddr);
            }
#pragma unroll
            for (int jn = 0; jn < 4; jn++)
#pragma unroll
                for (int i = 0; i < 2; i++) {
                    mma16816(acc[i][jn * 2 + 0], af[i], bf[jn]);
                    mma16816(acc[i][jn * 2 + 1], af[i], bf[jn] + 2);
                }
        }
    };

    stage(0); cp_commit();
    stage(1); cp_commit();

    // chunks 0..5: single barrier per chunk
#pragma unroll 1
    for (int c = 0; c < 6; c++) {
        cp_wait1();          // self: group c landed (committed 0..c+1, <=1 pending)
        __syncthreads();     // publish all threads' copies; orders compute(c-1) before stage(c+2)
        stage(c + 2); cp_commit();
        compute(c);
    }
    // tail
    cp_wait1();              // groups 0..6 done
    __syncthreads();
    compute(6);
    cp_wait0();              // group 7 done
    __syncthreads();
    compute(7);

    // ---- direct register scatter epilogue ----
    // mma m16n8 acc layout: thread holds rows {gid, gid+8}, cols {2*tig, 2*tig+1}
    const int gid = lane >> 2;
    const int tig = lane & 3;
#pragma unroll
    for (int i = 0; i < 2; i++) {
        int rbase = wm * 32 + i * 16 + gid;
        int o0 = out_s[rbase];
        int o1 = out_s[rbase + 8];
        OutT* p0 = (o0 >= 0) ? out + (size_t)o0 * CH + co0 + wn * 64 + 2 * tig : (OutT*)0;
        OutT* p1 = (o1 >= 0) ? out + (size_t)o1 * CH + co0 + wn * 64 + 2 * tig : (OutT*)0;
#pragma unroll
        for (int j = 0; j < 8; j++) {
            if (p0) scatter2(p0 + j * 8, acc[i][j][0], acc[i][j][1]);
            if (p1) scatter2(p1 + j * 8, acc[i][j][2], acc[i][j][3]);
        }
    }
}

// ---------------- launch ----------------
extern "C" void kernel_launch(void* const* d_in, const int* in_sizes, int n_in,
                              void* d_out, int out_size) {
    const float* feat   = (const float*)d_in[0];
    const int*   nbr    = (const int*)d_in[2];
    const float* W1     = (const float*)d_in[3];
    const float* gamma1 = (const float*)d_in[4];
    const float* beta1  = (const float*)d_in[5];
    const float* W2     = (const float*)d_in[6];
    const float* gamma2 = (const float*)d_in[7];
    const float* beta2  = (const float*)d_in[8];
    float* out = (float*)d_out;

    int n = in_sizes[0] / CH;
    if (n <= 0) return;

    __half *h, *wh1, *wh2;
    float *yf;
    int *cntp;
    cudaGetSymbolAddress((void**)&h,    g_h);
    cudaGetSymbolAddress((void**)&yf,   g_y);
    cudaGetSymbolAddress((void**)&wh1,  g_w1h);
    cudaGetSymbolAddress((void**)&wh2,  g_w2h);
    cudaGetSymbolAddress((void**)&cntp, g_cnt);
    __half* y = (__half*)yf;   // y used as fp16

    cudaFuncSetAttribute(conv_scatter<__half>, cudaFuncAttributeMaxDynamicSharedMemorySize, SMEM_TOT);
    cudaFuncSetAttribute(conv_scatter<float>,  cudaFuncAttributeMaxDynamicSharedMemorySize, SMEM_TOT);

    const int WTOT = KOFF * CH * CH;
    w2h_kernel<<<512, 256>>>(W1, wh1, W2, wh2, WTOT);

    cudaMemsetAsync(cntp, 0, KOFF * sizeof(int));
    build_pairs_kernel<<<(n + 255) / 256, 256>>>(nbr, n);

    int tpk = (n + BM - 1) / BM;
    dim3 cgrid(KOFF * tpk, 2);

    // stage 1: bn_apply fuses y zero-fill (fp16) AND residual init (out = feat)
    bn_stats_kernel<<<STATS_BLOCKS, 256>>>(feat, n);
    bn_finalize_kernel<<<CH, 128>>>(gamma1, beta1, n);
    bn_apply_kernel<<<2048, 256>>>(feat, h, feat, out, y, n);
    conv_scatter<__half><<<cgrid, 256, SMEM_TOT>>>(h, wh1, y, tpk);

    // stage 2: fp16 y -> stats + bn_apply; conv2 scatter-adds fp32 onto out
    bn_stats_h_kernel<<<STATS_BLOCKS, 256>>>(y, n);
    bn_finalize_kernel<<<CH, 128>>>(gamma2, beta2, n);
    bn_apply_h_kernel<<<2048, 256>>>(y, h, n);
    conv_scatter<float><<<cgrid, 256, SMEM_TOT>>>(h, wh2, out, tpk);
}

// round 17
// speedup vs baseline: 1.4125x; 1.0355x over previous
#include <cuda_runtime.h>
#include <cuda_fp16.h>
#include <cstdint>

#define CH    256
#define KOFF  27
#define MAXN  100000
#define BM    128      // pair-rows per CTA tile
#define KC    32       // K-chunk (8 chunks of 32 over CH=256)
#define NSTAGE 3
#define STATS_BLOCKS 512

// smem layout (bytes) — MUST stay <= ~60KB/CTA: occ-2 requires 2*SMEM <= ~128KB/SM
#define A_LDM     40                        // halfs: 32 + 8 pad
#define B_LDM     136                       // halfs: 128 + 8 pad
#define A_STAGE_B (BM * A_LDM * 2)          // 10240
#define B_STAGE_B (KC * B_LDM * 2)          // 8704
#define STAGE_B   (A_STAGE_B + B_STAGE_B)   // 18944  (3 stages = 56832)
#define OFF_LISTS (NSTAGE * STAGE_B)        // 56832
#define SMEM_TOT  (OFF_LISTS + 2 * BM * 4)  // 57856

// ---- scratch (device globals; allocation-free) ----
__device__ __half g_h [(size_t)MAXN * CH];     // bn_relu output (fp16)
__device__ __half g_y [(size_t)MAXN * CH];     // conv output accumulator (fp16)
__device__ __half g_w1h[(size_t)KOFF * CH * CH];
__device__ __half g_w2h[(size_t)KOFF * CH * CH];
__device__ int    g_cnt[KOFF];
__device__ int    g_pin [(size_t)KOFF * MAXN];
__device__ int    g_pout[(size_t)KOFF * MAXN];
__device__ float  g_part[2 * STATS_BLOCKS * CH];
__device__ float  g_scale[CH];
__device__ float  g_shift[CH];

__device__ __forceinline__ uint32_t smem_u32(const void* p) {
    uint32_t a;
    asm("{ .reg .u64 t; cvta.to.shared.u64 t, %1; cvt.u32.u64 %0, t; }" : "=r"(a) : "l"(p));
    return a;
}
__device__ __forceinline__ void cp16(uint32_t dst, const void* src, int src_size) {
    asm volatile("cp.async.cg.shared.global [%0], [%1], 16, %2;"
                 :: "r"(dst), "l"(src), "r"(src_size) : "memory");
}
__device__ __forceinline__ void cp_commit() {
    asm volatile("cp.async.commit_group;" ::: "memory");
}
__device__ __forceinline__ void cp_wait1() {
    asm volatile("cp.async.wait_group 1;" ::: "memory");
}
__device__ __forceinline__ void cp_wait0() {
    asm volatile("cp.async.wait_group 0;" ::: "memory");
}
__device__ __forceinline__ void scatter2(__half* p, float a, float b) {
    __half2 v = __floats2half2_rn(a, b);
    asm volatile("red.global.add.noftz.f16x2 [%0], %1;"
                 :: "l"(p), "r"(*(uint32_t*)&v) : "memory");
}
__device__ __forceinline__ void ldmx4(uint32_t* r, uint32_t addr) {
    asm volatile("ldmatrix.sync.aligned.m8n8.x4.shared.b16 {%0,%1,%2,%3}, [%4];"
                 : "=r"(r[0]), "=r"(r[1]), "=r"(r[2]), "=r"(r[3]) : "r"(addr));
}
__device__ __forceinline__ void ldmx4_t(uint32_t* r, uint32_t addr) {
    asm volatile("ldmatrix.sync.aligned.m8n8.x4.trans.shared.b16 {%0,%1,%2,%3}, [%4];"
                 : "=r"(r[0]), "=r"(r[1]), "=r"(r[2]), "=r"(r[3]) : "r"(addr));
}
__device__ __forceinline__ void mma16816(float* c, const uint32_t* a, const uint32_t* b) {
    asm volatile("mma.sync.aligned.m16n8k16.row.col.f32.f16.f16.f32 "
                 "{%0,%1,%2,%3}, {%4,%5,%6,%7}, {%8,%9}, {%0,%1,%2,%3};"
                 : "+f"(c[0]), "+f"(c[1]), "+f"(c[2]), "+f"(c[3])
                 : "r"(a[0]), "r"(a[1]), "r"(a[2]), "r"(a[3]), "r"(b[0]), "r"(b[1]));
}

// ---------------- BatchNorm stats (fp32 input) ----------------
__global__ void bn_stats_kernel(const float* __restrict__ x, int n) {
    __shared__ float4 sh[2][256];
    const int c4  = threadIdx.x & 63;
    const int sub = threadIdx.x >> 6;
    float4 s  = make_float4(0.f, 0.f, 0.f, 0.f);
    float4 s2 = make_float4(0.f, 0.f, 0.f, 0.f);
#pragma unroll 4
    for (int r = blockIdx.x * 4 + sub; r < n; r += gridDim.x * 4) {
        float4 v = *(const float4*)(x + (size_t)r * CH + c4 * 4);
        s.x += v.x; s.y += v.y; s.z += v.z; s.w += v.w;
        s2.x += v.x * v.x; s2.y += v.y * v.y; s2.z += v.z * v.z; s2.w += v.w * v.w;
    }
    sh[0][threadIdx.x] = s;
    sh[1][threadIdx.x] = s2;
    __syncthreads();
    if (sub == 0) {
#pragma unroll
        for (int i = 1; i < 4; i++) {
            float4 a = sh[0][c4 + 64 * i], b = sh[1][c4 + 64 * i];
            s.x += a.x; s.y += a.y; s.z += a.z; s.w += a.w;
            s2.x += b.x; s2.y += b.y; s2.z += b.z; s2.w += b.w;
        }
        *(float4*)(g_part + blockIdx.x * CH + c4 * 4) = s;
        *(float4*)(g_part + STATS_BLOCKS * CH + blockIdx.x * CH + c4 * 4) = s2;
    }
}

// ---------------- BatchNorm stats (fp16 input) ----------------
__global__ void bn_stats_h_kernel(const __half* __restrict__ x, int n) {
    __shared__ float4 sh[2][256];
    const int c4  = threadIdx.x & 63;
    const int sub = threadIdx.x >> 6;
    float4 s  = make_float4(0.f, 0.f, 0.f, 0.f);
    float4 s2 = make_float4(0.f, 0.f, 0.f, 0.f);
#pragma unroll 4
    for (int r = blockIdx.x * 4 + sub; r < n; r += gridDim.x * 4) {
        uint2 raw = *(const uint2*)(x + (size_t)r * CH + c4 * 4);
        float2 f0 = __half22float2(*(__half2*)&raw.x);
        float2 f1 = __half22float2(*(__half2*)&raw.y);
        s.x += f0.x; s.y += f0.y; s.z += f1.x; s.w += f1.y;
        s2.x += f0.x * f0.x; s2.y += f0.y * f0.y; s2.z += f1.x * f1.x; s2.w += f1.y * f1.y;
    }
    sh[0][threadIdx.x] = s;
    sh[1][threadIdx.x] = s2;
    __syncthreads();
    if (sub == 0) {
#pragma unroll
        for (int i = 1; i < 4; i++) {
            float4 a = sh[0][c4 + 64 * i], b = sh[1][c4 + 64 * i];
            s.x += a.x; s.y += a.y; s.z += a.z; s.w += a.w;
            s2.x += b.x; s2.y += b.y; s2.z += b.z; s2.w += b.w;
        }
        *(float4*)(g_part + blockIdx.x * CH + c4 * 4) = s;
        *(float4*)(g_part + STATS_BLOCKS * CH + blockIdx.x * CH + c4 * 4) = s2;
    }
}

__global__ void bn_finalize_kernel(const float* __restrict__ gamma,
                                   const float* __restrict__ beta, int n) {
    __shared__ float rs[128], rs2[128];
    int c = blockIdx.x, t = threadIdx.x;
    float s = 0.f, s2 = 0.f;
    for (int b = t; b < STATS_BLOCKS; b += 128) {
        s  += g_part[b * CH + c];
        s2 += g_part[STATS_BLOCKS * CH + b * CH + c];
    }
    rs[t] = s; rs2[t] = s2;
    __syncthreads();
    for (int w = 64; w > 0; w >>= 1) {
        if (t < w) { rs[t] += rs[t + w]; rs2[t] += rs2[t + w]; }
        __syncthreads();
    }
    if (t == 0) {
        float mean = rs[0] / (float)n;
        float var  = rs2[0] / (float)n - mean * mean;
        float rstd = rsqrtf(var + 1e-4f);
        float sc = gamma[c] * rstd;
        g_scale[c] = sc;
        g_shift[c] = beta[c] - mean * sc;
    }
}

// stage1: bn+relu fp32 feat -> fp16 h; fuses fp16 zero-fill of y
__global__ void bn_apply_kernel(const float* __restrict__ x, __half* __restrict__ y,
                                __half* __restrict__ zdst, int n) {
    size_t total4 = (size_t)n * CH / 4;
    for (size_t i = (size_t)blockIdx.x * blockDim.x + threadIdx.x; i < total4;
         i += (size_t)gridDim.x * blockDim.x) {
        int c0 = (int)(i & (CH / 4 - 1)) * 4;
        float4 v  = ((const float4*)x)[i];
        float4 sc = *(const float4*)(g_scale + c0);
        float4 sh = *(const float4*)(g_shift + c0);
        float a = fmaxf(fmaf(v.x, sc.x, sh.x), 0.f);
        float b = fmaxf(fmaf(v.y, sc.y, sh.y), 0.f);
        float c = fmaxf(fmaf(v.z, sc.z, sh.z), 0.f);
        float d = fmaxf(fmaf(v.w, sc.w, sh.w), 0.f);
        __half2* y2 = (__half2*)(y + i * 4);
        y2[0] = __floats2half2_rn(a, b);
        y2[1] = __floats2half2_rn(c, d);
        ((uint2*)zdst)[i] = make_uint2(0u, 0u);
    }
}

// stage2: bn+relu fp16 y -> fp16 h; re-zeros y in place after reading (conv2 accumulates there)
__global__ void bn_apply_h_kernel(__half* __restrict__ x, __half* __restrict__ y, int n) {
    size_t total4 = (size_t)n * CH / 4;
    for (size_t i = (size_t)blockIdx.x * blockDim.x + threadIdx.x; i < total4;
         i += (size_t)gridDim.x * blockDim.x) {
        int c0 = (int)(i & (CH / 4 - 1)) * 4;
        uint2 raw = ((const uint2*)x)[i];
        float2 f0 = __half22float2(*(__half2*)&raw.x);
        float2 f1 = __half22float2(*(__half2*)&raw.y);
        float4 sc = *(const float4*)(g_scale + c0);
        float4 sh = *(const float4*)(g_shift + c0);
        float a = fmaxf(fmaf(f0.x, sc.x, sh.x), 0.f);
        float b = fmaxf(fmaf(f0.y, sc.y, sh.y), 0.f);
        float c = fmaxf(fmaf(f1.x, sc.z, sh.z), 0.f);
        float d = fmaxf(fmaf(f1.y, sc.w, sh.w), 0.f);
        __half2* y2 = (__half2*)(y + i * 4);
        y2[0] = __floats2half2_rn(a, b);
        y2[1] = __floats2half2_rn(c, d);
        ((uint2*)x)[i] = make_uint2(0u, 0u);   // re-zero y for conv2's fp16 scatter
    }
}

// final: out = feat + y (conv2 accumulator), fp32 output
__global__ void final_add_kernel(const float* __restrict__ feat, const __half* __restrict__ y,
                                 float* __restrict__ out, int n) {
    size_t total4 = (size_t)n * CH / 4;
    for (size_t i = (size_t)blockIdx.x * blockDim.x + threadIdx.x; i < total4;
         i += (size_t)gridDim.x * blockDim.x) {
        float4 f = ((const float4*)feat)[i];
        uint2 raw = ((const uint2*)y)[i];
        float2 y0 = __half22float2(*(__half2*)&raw.x);
        float2 y1 = __half22float2(*(__half2*)&raw.y);
        f.x += y0.x; f.y += y0.y; f.z += y1.x; f.w += y1.y;
        ((float4*)out)[i] = f;
    }
}

// convert BOTH weight tensors in one launch
__global__ void w2h_kernel(const float* __restrict__ W1, __half* __restrict__ Wh1,
                           const float* __restrict__ W2, __half* __restrict__ Wh2, int total) {
    for (int i = blockIdx.x * blockDim.x + threadIdx.x; i < total;
         i += gridDim.x * blockDim.x) {
        Wh1[i] = __float2half_rn(W1[i]);
        Wh2[i] = __float2half_rn(W2[i]);
    }
}

// ---- rule lists: per offset k, compact (in,out) pairs where neighbor exists ----
__global__ void build_pairs_kernel(const int* __restrict__ nbr, int n) {
    __shared__ int cnt_l[KOFF];
    __shared__ int base_l[KOFF];
    __shared__ short lpos[256 * KOFF];
    int t = threadIdx.x;
    int p = blockIdx.x * 256 + t;
    if (t < KOFF) cnt_l[t] = 0;
    __syncthreads();
    int nb[KOFF];
    if (p < n) {
#pragma unroll
        for (int k = 0; k < KOFF; k++) {
            nb[k] = nbr[p * KOFF + k];
            if (nb[k] >= 0) lpos[t * KOFF + k] = (short)atomicAdd(&cnt_l[k], 1);
        }
    }
    __syncthreads();
    if (t < KOFF) base_l[t] = atomicAdd(&g_cnt[t], cnt_l[t]);
    __syncthreads();
    if (p < n) {
#pragma unroll
        for (int k = 0; k < KOFF; k++) {
            if (nb[k] >= 0) {
                int pos = base_l[k] + (int)lpos[t * KOFF + k];
                g_pin [k * MAXN + pos] = nb[k];
                g_pout[k * MAXN + pos] = p;
            }
        }
    }
}

// ---------------- gather-GEMM-scatter sparse conv (fp16 scatter target) ----------------
// grid: (tiles_per_k * KOFF [mt-major], 2 cout halves). CTA: 256 thr, tile 128 pairs x 128 cout.
// mma.sync m16n8k16 + direct register scatter epilogue (red.global.add.noftz.f16x2).
// 3-stage cp.async pipeline, single barrier per chunk:
//   wait1 -> sync -> stage(c+2) -> commit -> compute(c)
__global__ __launch_bounds__(256, 2)
void conv_scatter(const __half* __restrict__ x, const __half* __restrict__ W,
                  __half* __restrict__ out, int tpk)
{
    extern __shared__ char dyn[];
    const int tid  = threadIdx.x;
    const int wid  = tid >> 5;
    const int lane = tid & 31;
    const int k    = blockIdx.x % KOFF;       // mt-major: empty tiles cluster in tail waves
    const int mt   = blockIdx.x / KOFF;
    const int cnt  = g_cnt[k];
    const int m0   = mt * BM;
    if (m0 >= cnt) return;
    const int rows = min(BM, cnt - m0);
    const int co0  = blockIdx.y * 128;

    int* in_s  = (int*)(dyn + OFF_LISTS);
    int* out_s = in_s + BM;
    const uint32_t base_u = smem_u32(dyn);

    if (tid < BM) {
        int ok = tid < rows;
        in_s [tid] = ok ? g_pin [k * MAXN + m0 + tid] : -1;
        out_s[tid] = ok ? g_pout[k * MAXN + m0 + tid] : -1;
    }
    __syncthreads();

    const __half* wk = W + (size_t)k * CH * CH;

    auto stage = [&](int c) {
        int buf = c % NSTAGE;
        int kc  = c * KC;
        uint32_t a_u = base_u + buf * STAGE_B;
        uint32_t b_u = a_u + A_STAGE_B;
#pragma unroll
        for (int i = 0; i < 2; i++) {          // A: 512 x 16B
            int idx = tid + i * 256;
            int row = idx >> 2, c16 = idx & 3;
            int in = in_s[row];
            uint32_t dst = a_u + row * (A_LDM * 2) + c16 * 16;
            const __half* src = x + ((size_t)(in < 0 ? 0 : in) * CH + kc + c16 * 8);
            cp16(dst, src, in < 0 ? 0 : 16);
        }
#pragma unroll
        for (int i = 0; i < 2; i++) {          // B: 512 x 16B (32 rows x 128 cols)
            int idx = tid + i * 256;
            int row = idx >> 4, c16 = idx & 15;
            uint32_t dst = b_u + row * (B_LDM * 2) + c16 * 16;
            const __half* src = wk + ((size_t)(kc + row) * CH + co0 + c16 * 8);
            cp16(dst, src, 16);
        }
    };

    // accumulators: 2 m16 blocks x 8 n8 tiles x 4 floats
    float acc[2][8][4];
#pragma unroll
    for (int i = 0; i < 2; i++)
#pragma unroll
        for (int j = 0; j < 8; j++)
#pragma unroll
            for (int e = 0; e < 4; e++) acc[i][j][e] = 0.f;

    const int wm = wid & 3;      // 32-row group
    const int wn = wid >> 2;     // 64-col group (0..1)

    auto compute = [&](int c) {
        uint32_t a_u = base_u + (c % NSTAGE) * STAGE_B;
        uint32_t b_u = a_u + A_STAGE_B;
#pragma unroll
        for (int kk = 0; kk < KC; kk += 16) {
            uint32_t af[2][4];
            uint32_t bf[4][4];
#pragma unroll
            for (int i = 0; i < 2; i++) {
                uint32_t addr = a_u + ((wm * 32 + i * 16 + (lane & 15)) * A_LDM
                                       + kk + ((lane >> 4) << 3)) * 2;
                ldmx4(af[i], addr);
            }
#pragma unroll
            for (int jn = 0; jn < 4; jn++) {
                uint32_t baddr = b_u + ((kk + (lane & 15)) * B_LDM
                                        + wn * 64 + jn * 16 + ((lane >> 4) << 3)) * 2;
                ldmx4_t(bf[jn], baddr);
            }
#pragma unroll
            for (int jn = 0; jn < 4; jn++)
#pragma unroll
                for (int i = 0; i < 2; i++) {
                    mma16816(acc[i][jn * 2 + 0], af[i], bf[jn]);
                    mma16816(acc[i][jn * 2 + 1], af[i], bf[jn] + 2);
                }
        }
    };

    stage(0); cp_commit();
    stage(1); cp_commit();

    // chunks 0..5: single barrier per chunk
#pragma unroll 1
    for (int c = 0; c < 6; c++) {
        cp_wait1();          // self: group c landed (committed 0..c+1, <=1 pending)
        __syncthreads();     // publish all threads' copies; orders compute(c-1) before stage(c+2)
        stage(c + 2); cp_commit();
        compute(c);
    }
    // tail
    cp_wait1();              // groups 0..6 done
    __syncthreads();
    compute(6);
    cp_wait0();              // group 7 done
    __syncthreads();
    compute(7);

    // ---- direct register scatter epilogue (fp16x2 reds) ----
    // mma m16n8 acc layout: thread holds rows {gid, gid+8}, cols {2*tig, 2*tig+1}
    const int gid = lane >> 2;
    const int tig = lane & 3;
#pragma unroll
    for (int i = 0; i < 2; i++) {
        int rbase = wm * 32 + i * 16 + gid;
        int o0 = out_s[rbase];
        int o1 = out_s[rbase + 8];
        __half* p0 = (o0 >= 0) ? out + (size_t)o0 * CH + co0 + wn * 64 + 2 * tig : (__half*)0;
        __half* p1 = (o1 >= 0) ? out + (size_t)o1 * CH + co0 + wn * 64 + 2 * tig : (__half*)0;
#pragma unroll
        for (int j = 0; j < 8; j++) {
            if (p0) scatter2(p0 + j * 8, acc[i][j][0], acc[i][j][1]);
            if (p1) scatter2(p1 + j * 8, acc[i][j][2], acc[i][j][3]);
        }
    }
}

// ---------------- launch ----------------
extern "C" void kernel_launch(void* const* d_in, const int* in_sizes, int n_in,
                              void* d_out, int out_size) {
    const float* feat   = (const float*)d_in[0];
    const int*   nbr    = (const int*)d_in[2];
    const float* W1     = (const float*)d_in[3];
    const float* gamma1 = (const float*)d_in[4];
    const float* beta1  = (const float*)d_in[5];
    const float* W2     = (const float*)d_in[6];
    const float* gamma2 = (const float*)d_in[7];
    const float* beta2  = (const float*)d_in[8];
    float* out = (float*)d_out;

    int n = in_sizes[0] / CH;
    if (n <= 0) return;

    __half *h, *y, *wh1, *wh2;
    int *cntp;
    cudaGetSymbolAddress((void**)&h,    g_h);
    cudaGetSymbolAddress((void**)&y,    g_y);
    cudaGetSymbolAddress((void**)&wh1,  g_w1h);
    cudaGetSymbolAddress((void**)&wh2,  g_w2h);
    cudaGetSymbolAddress((void**)&cntp, g_cnt);

    cudaFuncSetAttribute(conv_scatter, cudaFuncAttributeMaxDynamicSharedMemorySize, SMEM_TOT);

    const int WTOT = KOFF * CH * CH;
    w2h_kernel<<<512, 256>>>(W1, wh1, W2, wh2, WTOT);

    cudaMemsetAsync(cntp, 0, KOFF * sizeof(int));
    build_pairs_kernel<<<(n + 255) / 256, 256>>>(nbr, n);

    int tpk = (n + BM - 1) / BM;
    dim3 cgrid(KOFF * tpk, 2);

    // stage 1: bn_apply (feat->h) fuses y zero-fill; conv1 fp16-scatters into y
    bn_stats_kernel<<<STATS_BLOCKS, 256>>>(feat, n);
    bn_finalize_kernel<<<CH, 128>>>(gamma1, beta1, n);
    bn_apply_kernel<<<2048, 256>>>(feat, h, y, n);
    conv_scatter<<<cgrid, 256, SMEM_TOT>>>(h, wh1, y, tpk);

    // stage 2: bn over fp16 y -> h (re-zeros y); conv2 fp16-scatters into y;
    // final: out = feat + y
    bn_stats_h_kernel<<<STATS_BLOCKS, 256>>>(y, n);
    bn_finalize_kernel<<<CH, 128>>>(gamma2, beta2, n);
    bn_apply_h_kernel<<<2048, 256>>>(y, h, n);
    conv_scatter<<<cgrid, 256, SMEM_TOT>>>(h, wh2, y, tpk);
    final_add_kernel<<<2048, 256>>>(feat, y, out, n);
}